// round 1
// baseline (speedup 1.0000x reference)
#include <cuda_runtime.h>
#include <math.h>

#define Bb 4
#define Ss 2048
#define Dd 1024

// Scratch (allocation-free rule: __device__ globals)
__device__ float g_Q[Bb * Ss * Dd];
__device__ float g_K[Bb * Ss * Dd];
__device__ float g_V[Bb * Ss * Dd];
__device__ float g_P[Bb * Ss * Ss];

#define BM 128
#define BN 128
#define BK 16
#define TM 8
#define TN 8
// 256 threads: (BM/TM)*(BN/TN)

template <bool TRANS_B, bool ADD_BIAS>
__global__ __launch_bounds__(256, 2) void gemm_kernel(
    const float* __restrict__ A, const float* __restrict__ Bm,
    const float* __restrict__ bias, float* __restrict__ C,
    int M, int N, int K, float alpha,
    long long sA, long long sB, long long sC)
{
    __shared__ float As[BK][BM + 4];
    __shared__ float Bs[BK][BN + 4];

    const int bz = blockIdx.z;
    A  += (long long)bz * sA;
    Bm += (long long)bz * sB;
    C  += (long long)bz * sC;

    const int rowBase = blockIdx.y * BM;
    const int colBase = blockIdx.x * BN;

    const int tid = threadIdx.x;
    const int tx = tid & 15;   // 0..15 -> col group
    const int ty = tid >> 4;   // 0..15 -> row group

    // A-tile loader mapping: 128 rows x 16 cols, float4, 2 rows per thread
    const int ar = tid >> 2;          // 0..63
    const int ac = (tid & 3) << 2;    // 0,4,8,12
    // NN B-tile loader mapping: 16 rows x 128 cols, float4
    const int nr = tid >> 5;          // 0..7
    const int nc = (tid & 31) << 2;   // 0..124

    float acc[TM][TN];
#pragma unroll
    for (int i = 0; i < TM; i++)
#pragma unroll
        for (int j = 0; j < TN; j++) acc[i][j] = 0.0f;

    for (int k0 = 0; k0 < K; k0 += BK) {
        // Load A tile (transposed into smem for K-major inner loop)
#pragma unroll
        for (int i = 0; i < 2; i++) {
            const int r = ar + i * 64;
            const float4 v = *reinterpret_cast<const float4*>(
                A + (long long)(rowBase + r) * K + k0 + ac);
            As[ac + 0][r] = v.x;
            As[ac + 1][r] = v.y;
            As[ac + 2][r] = v.z;
            As[ac + 3][r] = v.w;
        }
        if (TRANS_B) {
            // B is [N, K] row-major; same transposed-load pattern as A
#pragma unroll
            for (int i = 0; i < 2; i++) {
                const int r = ar + i * 64;
                const float4 v = *reinterpret_cast<const float4*>(
                    Bm + (long long)(colBase + r) * K + k0 + ac);
                Bs[ac + 0][r] = v.x;
                Bs[ac + 1][r] = v.y;
                Bs[ac + 2][r] = v.z;
                Bs[ac + 3][r] = v.w;
            }
        } else {
            // B is [K, N] row-major; direct coalesced float4 copy
#pragma unroll
            for (int i = 0; i < 2; i++) {
                const int r = nr + i * 8;
                const float4 v = *reinterpret_cast<const float4*>(
                    Bm + (long long)(k0 + r) * N + colBase + nc);
                *reinterpret_cast<float4*>(&Bs[r][nc]) = v;
            }
        }
        __syncthreads();

#pragma unroll
        for (int k = 0; k < BK; k++) {
            float a[TM], b[TN];
            *reinterpret_cast<float4*>(&a[0]) =
                *reinterpret_cast<const float4*>(&As[k][ty * TM]);
            *reinterpret_cast<float4*>(&a[4]) =
                *reinterpret_cast<const float4*>(&As[k][ty * TM + 4]);
            *reinterpret_cast<float4*>(&b[0]) =
                *reinterpret_cast<const float4*>(&Bs[k][tx * TN]);
            *reinterpret_cast<float4*>(&b[4]) =
                *reinterpret_cast<const float4*>(&Bs[k][tx * TN + 4]);
#pragma unroll
            for (int i = 0; i < TM; i++)
#pragma unroll
                for (int j = 0; j < TN; j++)
                    acc[i][j] = fmaf(a[i], b[j], acc[i][j]);
        }
        __syncthreads();
    }

    // Epilogue: alpha scale (+ optional bias), vectorized stores
#pragma unroll
    for (int i = 0; i < TM; i++) {
        const long long row = rowBase + ty * TM + i;
#pragma unroll
        for (int j = 0; j < TN; j += 4) {
            const int col = colBase + tx * TN + j;
            float4 v;
            v.x = acc[i][j + 0] * alpha;
            v.y = acc[i][j + 1] * alpha;
            v.z = acc[i][j + 2] * alpha;
            v.w = acc[i][j + 3] * alpha;
            if (ADD_BIAS) {
                const float4 bv = *reinterpret_cast<const float4*>(bias + col);
                v.x += bv.x; v.y += bv.y; v.z += bv.z; v.w += bv.w;
            }
            *reinterpret_cast<float4*>(C + row * N + col) = v;
        }
    }
}

// Row softmax over the last dim (Ss = 2048) of g_P. One block per row.
__global__ __launch_bounds__(256) void softmax_kernel(float* __restrict__ P)
{
    float* row = P + (long long)blockIdx.x * Ss;
    const int tid = threadIdx.x;
    const int w = tid >> 5, l = tid & 31;

    float v[8];
    float m = -1e30f;
#pragma unroll
    for (int i = 0; i < 8; i++) {
        v[i] = row[tid + i * 256];
        m = fmaxf(m, v[i]);
    }
#pragma unroll
    for (int o = 16; o > 0; o >>= 1)
        m = fmaxf(m, __shfl_xor_sync(0xFFFFFFFFu, m, o));

    __shared__ float smax[8];
    __shared__ float ssum[8];
    if (l == 0) smax[w] = m;
    __syncthreads();
    m = smax[0];
#pragma unroll
    for (int i = 1; i < 8; i++) m = fmaxf(m, smax[i]);

    float s = 0.0f;
#pragma unroll
    for (int i = 0; i < 8; i++) {
        v[i] = __expf(v[i] - m);
        s += v[i];
    }
#pragma unroll
    for (int o = 16; o > 0; o >>= 1)
        s += __shfl_xor_sync(0xFFFFFFFFu, s, o);
    if (l == 0) ssum[w] = s;
    __syncthreads();
    float tot = 0.0f;
#pragma unroll
    for (int i = 0; i < 8; i++) tot += ssum[i];
    const float inv = 1.0f / tot;
#pragma unroll
    for (int i = 0; i < 8; i++)
        row[tid + i * 256] = v[i] * inv;
}

extern "C" void kernel_launch(void* const* d_in, const int* in_sizes, int n_in,
                              void* d_out, int out_size)
{
    const float* x  = (const float*)d_in[0];
    const float* Wq = (const float*)d_in[1];
    const float* bq = (const float*)d_in[2];
    const float* Wk = (const float*)d_in[3];
    const float* bk = (const float*)d_in[4];
    const float* Wv = (const float*)d_in[5];
    const float* bv = (const float*)d_in[6];
    float* out = (float*)d_out;

    float *Q, *K, *V, *P;
    cudaGetSymbolAddress((void**)&Q, g_Q);
    cudaGetSymbolAddress((void**)&K, g_K);
    cudaGetSymbolAddress((void**)&V, g_V);
    cudaGetSymbolAddress((void**)&P, g_P);

    const dim3 blk(256);
    const long long SD = (long long)Ss * Dd;
    const long long SS2 = (long long)Ss * Ss;

    // 1) QKV projections: [8192,1024] = x[8192,1024] @ W[1024,1024]^T + b
    const dim3 g1(Dd / BN, (Bb * Ss) / BM, 1);
    gemm_kernel<true, true><<<g1, blk>>>(x, Wq, bq, Q, Bb * Ss, Dd, Dd, 1.0f, 0, 0, 0);
    gemm_kernel<true, true><<<g1, blk>>>(x, Wk, bk, K, Bb * Ss, Dd, Dd, 1.0f, 0, 0, 0);
    gemm_kernel<true, true><<<g1, blk>>>(x, Wv, bv, V, Bb * Ss, Dd, Dd, 1.0f, 0, 0, 0);

    // 2) scores[b] = (Q[b] @ K[b]^T) * (1/sqrt(D)), batched over blockIdx.z
    const dim3 g2(Ss / BN, Ss / BM, Bb);
    gemm_kernel<true, false><<<g2, blk>>>(Q, K, nullptr, P, Ss, Ss, Dd, 0.03125f,
                                          SD, SD, SS2);

    // 3) row softmax
    softmax_kernel<<<Bb * Ss, 256>>>(P);

    // 4) out[b] = P[b] @ V[b]
    const dim3 g3(Dd / BN, Ss / BM, Bb);
    gemm_kernel<false, false><<<g3, blk>>>(P, V, nullptr, out, Ss, Dd, Ss, 1.0f,
                                           SS2, SD, SD);
}

// round 3
// speedup vs baseline: 3.6599x; 3.6599x over previous
#include <cuda_runtime.h>
#include <cstdint>

#define Bb 4
#define Ss 2048
#define Dd 1024

#define BM 128
#define BN 128
#define BK 32
#define STAGES 3
#define STAGE_FLOATS (BM * BK + BN * BK)     // 8192 floats = 32KB
#define STAGE_BYTES  (STAGE_FLOATS * 4)
#define A_BYTES      (BM * BK * 4)           // 16KB

// ---------------- device scratch (allocation-free rule) ----------------
__device__ __align__(1024) float g_xr[Bb * Ss * Dd];
__device__ __align__(1024) float g_Wr[3 * Dd * Dd];
__device__ __align__(1024) float g_Q[Bb * Ss * Dd];
__device__ __align__(1024) float g_K[Bb * Ss * Dd];
__device__ __align__(1024) float g_V[Bb * Ss * Dd];
__device__ __align__(1024) float g_Vt[Bb * Ss * Dd];
__device__ __align__(1024) float g_P[Bb * Ss * Ss];

// ---------------- helpers ----------------
__device__ __forceinline__ uint32_t smem_u32(const void* p) {
    uint32_t a;
    asm("{ .reg .u64 t; cvta.to.shared.u64 t, %1; cvt.u32.u64 %0, t; }" : "=r"(a) : "l"(p));
    return a;
}
__device__ __forceinline__ float rna_tf32(float f) {
    uint32_t u;
    asm("cvt.rna.tf32.f32 %0, %1;" : "=r"(u) : "f"(f));
    return __uint_as_float(u);
}
__device__ __forceinline__ void cp16(uint32_t dst, const void* src) {
    asm volatile("cp.async.cg.shared.global [%0], [%1], 16;" :: "r"(dst), "l"(src));
}
__device__ __forceinline__ void cp_commit() {
    asm volatile("cp.async.commit_group;" ::: "memory");
}
__device__ __forceinline__ void cp_wait1() {
    asm volatile("cp.async.wait_group 1;" ::: "memory");
}
__device__ __forceinline__ void ldsm4(uint32_t& r0, uint32_t& r1, uint32_t& r2, uint32_t& r3,
                                      uint32_t addr) {
    asm volatile("ldmatrix.sync.aligned.m8n8.x4.shared.b16 {%0,%1,%2,%3}, [%4];"
                 : "=r"(r0), "=r"(r1), "=r"(r2), "=r"(r3) : "r"(addr));
}
__device__ __forceinline__ void mma_tf32(float* c, const uint32_t* a, uint32_t b0, uint32_t b1) {
    asm volatile(
        "mma.sync.aligned.m16n8k8.row.col.f32.tf32.tf32.f32 "
        "{%0,%1,%2,%3}, {%4,%5,%6,%7}, {%8,%9}, {%0,%1,%2,%3};"
        : "+f"(c[0]), "+f"(c[1]), "+f"(c[2]), "+f"(c[3])
        : "r"(a[0]), "r"(a[1]), "r"(a[2]), "r"(a[3]), "r"(b0), "r"(b1));
}

// ---------------- tf32 mma.sync GEMM:  C[M,N] = A[M,K] @ B[N,K]^T * alpha (+bias) ----------------
template <bool BIAS, bool ROUND>
__global__ void __launch_bounds__(256, 2) mma_gemm(
    const float* __restrict__ A, const float* __restrict__ Bm,
    const float* __restrict__ bias, float* __restrict__ C,
    int Ntot, int Ktot, float alpha,
    long long sA, long long sB, long long sC)
{
    extern __shared__ __align__(1024) char smem[];
    const uint32_t sb = smem_u32(smem);

    const int tid = threadIdx.x;
    const int lane = tid & 31;
    const int wid = tid >> 5;
    const int wm = wid & 1;        // 2 warps in M
    const int wn = wid >> 1;       // 4 warps in N

    const int rowBase = blockIdx.y * BM;
    const int colBase = blockIdx.x * BN;
    const float* Ab = A + blockIdx.z * sA + (long long)rowBase * Ktot;
    const float* Bg0 = Bm + blockIdx.z * sB + (long long)colBase * Ktot;

    // loader mapping: 32 rows x 8 chunks(16B) per pass, 4 passes per tile
    const int lr = tid >> 3;       // 0..31
    const int lc = tid & 7;        // 0..7

    // fragment addressing
    const int frow = lane & 15;
    const int fkc = lane >> 4;     // selects k chunk within the k8 pair

    float acc[4][4][4];
#pragma unroll
    for (int i = 0; i < 4; i++)
#pragma unroll
        for (int j = 0; j < 4; j++)
#pragma unroll
            for (int q = 0; q < 4; q++) acc[i][j][q] = 0.0f;

    const int kIters = Ktot / BK;

    auto load_stage = [&](int buf, int kt) {
        const uint32_t sbase = sb + buf * STAGE_BYTES;
        const float* Ag = Ab + kt * BK;
        const float* Bg = Bg0 + kt * BK;
#pragma unroll
        for (int p = 0; p < 4; p++) {
            const int row = lr + 32 * p;
            const uint32_t off = row * 128 + ((uint32_t)(lc ^ (row & 7)) << 4);
            cp16(sbase + off, Ag + (long long)row * Ktot + lc * 4);
            cp16(sbase + A_BYTES + off, Bg + (long long)row * Ktot + lc * 4);
        }
    };

#pragma unroll
    for (int s = 0; s < STAGES - 1; s++) {
        if (s < kIters) load_stage(s, s);
        cp_commit();
    }

    int arow[4], brow[2];
#pragma unroll
    for (int mt = 0; mt < 4; mt++) arow[mt] = wm * 64 + mt * 16 + frow;
#pragma unroll
    for (int p = 0; p < 2; p++) brow[p] = wn * 32 + p * 16 + frow;

    for (int it = 0; it < kIters; it++) {
        cp_wait1();
        __syncthreads();

        const int nx = it + STAGES - 1;
        if (nx < kIters) load_stage(nx % STAGES, nx);
        cp_commit();

        const uint32_t As = sb + (it % STAGES) * STAGE_BYTES;
        const uint32_t Bs = As + A_BYTES;

#pragma unroll
        for (int ks = 0; ks < 4; ks++) {
            const int chunk = 2 * ks + fkc;
            uint32_t a[4][4];
#pragma unroll
            for (int mt = 0; mt < 4; mt++) {
                const uint32_t ad = As + arow[mt] * 128 +
                                    ((uint32_t)(chunk ^ (arow[mt] & 7)) << 4);
                ldsm4(a[mt][0], a[mt][1], a[mt][2], a[mt][3], ad);
            }
            uint32_t b[2][4];
#pragma unroll
            for (int p = 0; p < 2; p++) {
                const uint32_t bd = Bs + brow[p] * 128 +
                                    ((uint32_t)(chunk ^ (brow[p] & 7)) << 4);
                ldsm4(b[p][0], b[p][1], b[p][2], b[p][3], bd);
            }
#pragma unroll
            for (int mt = 0; mt < 4; mt++)
#pragma unroll
                for (int nt = 0; nt < 4; nt++) {
                    const int p = nt >> 1, o = nt & 1;
                    mma_tf32(acc[mt][nt], a[mt], b[p][o], b[p][2 + o]);
                }
        }
        __syncthreads();
    }

    // ---- epilogue ----
    const int g = lane >> 2;
    const int cpair = (lane & 3) * 2;
    float* Cb = C + blockIdx.z * sC;
#pragma unroll
    for (int mt = 0; mt < 4; mt++) {
#pragma unroll
        for (int nt = 0; nt < 4; nt++) {
            const int col = colBase + wn * 32 + nt * 8 + cpair;
            float bx = 0.f, by = 0.f;
            if (BIAS) { bx = bias[col]; by = bias[col + 1]; }
            const long long r0 = rowBase + wm * 64 + mt * 16 + g;
            const long long r1 = r0 + 8;
            float2 v0, v1;
            v0.x = acc[mt][nt][0] * alpha + bx;
            v0.y = acc[mt][nt][1] * alpha + by;
            v1.x = acc[mt][nt][2] * alpha + bx;
            v1.y = acc[mt][nt][3] * alpha + by;
            if (ROUND) {
                v0.x = rna_tf32(v0.x); v0.y = rna_tf32(v0.y);
                v1.x = rna_tf32(v1.x); v1.y = rna_tf32(v1.y);
            }
            *reinterpret_cast<float2*>(Cb + r0 * Ntot + col) = v0;
            *reinterpret_cast<float2*>(Cb + r1 * Ntot + col) = v1;
        }
    }
}

// ---------------- prep: round to tf32 (RNA) ----------------
__global__ void rna_kernel(const float* __restrict__ in, float* __restrict__ out, int n4)
{
    int i = blockIdx.x * blockDim.x + threadIdx.x;
    if (i >= n4) return;
    float4 v = reinterpret_cast<const float4*>(in)[i];
    v.x = rna_tf32(v.x); v.y = rna_tf32(v.y); v.z = rna_tf32(v.z); v.w = rna_tf32(v.w);
    reinterpret_cast<float4*>(out)[i] = v;
}

// ---------------- V transpose: Vt[b][e][s] = V[b][s][e] ----------------
__global__ void transpose_kernel(const float* __restrict__ V, float* __restrict__ Vt)
{
    __shared__ float t[32][33];
    const int b = blockIdx.z;
    const int s0 = blockIdx.x * 32, e0 = blockIdx.y * 32;
    const float* Vb = V + (long long)b * Ss * Dd;
    float* Vtb = Vt + (long long)b * Ss * Dd;
    const int x = threadIdx.x, y = threadIdx.y;
#pragma unroll
    for (int i = 0; i < 4; i++)
        t[y + 8 * i][x] = Vb[(long long)(s0 + y + 8 * i) * Dd + e0 + x];
    __syncthreads();
#pragma unroll
    for (int i = 0; i < 4; i++)
        Vtb[(long long)(e0 + y + 8 * i) * Ss + s0 + x] = t[x][y + 8 * i];
}

// ---------------- row softmax over S=2048, tf32-rounded output ----------------
__global__ void __launch_bounds__(256) softmax_kernel(float* __restrict__ P)
{
    float* row = P + (long long)blockIdx.x * Ss;
    const int tid = threadIdx.x;
    const int w = tid >> 5, l = tid & 31;

    float v[8];
    float m = -1e30f;
#pragma unroll
    for (int i = 0; i < 8; i++) { v[i] = row[tid + i * 256]; m = fmaxf(m, v[i]); }
#pragma unroll
    for (int o = 16; o > 0; o >>= 1) m = fmaxf(m, __shfl_xor_sync(0xFFFFFFFFu, m, o));

    __shared__ float smax[8], ssum[8];
    if (l == 0) smax[w] = m;
    __syncthreads();
    m = smax[0];
#pragma unroll
    for (int i = 1; i < 8; i++) m = fmaxf(m, smax[i]);

    float s = 0.0f;
#pragma unroll
    for (int i = 0; i < 8; i++) { v[i] = __expf(v[i] - m); s += v[i]; }
#pragma unroll
    for (int o = 16; o > 0; o >>= 1) s += __shfl_xor_sync(0xFFFFFFFFu, s, o);
    if (l == 0) ssum[w] = s;
    __syncthreads();
    float tot = 0.0f;
#pragma unroll
    for (int i = 0; i < 8; i++) tot += ssum[i];
    const float inv = 1.0f / tot;
#pragma unroll
    for (int i = 0; i < 8; i++) row[tid + i * 256] = rna_tf32(v[i] * inv);
}

// ---------------- host ----------------
extern "C" void kernel_launch(void* const* d_in, const int* in_sizes, int n_in,
                              void* d_out, int out_size)
{
    const float* x  = (const float*)d_in[0];
    const float* Wq = (const float*)d_in[1];
    const float* bq = (const float*)d_in[2];
    const float* Wk = (const float*)d_in[3];
    const float* bk = (const float*)d_in[4];
    const float* Wv = (const float*)d_in[5];
    const float* bv = (const float*)d_in[6];
    float* out = (float*)d_out;

    float *xr, *Wr, *Q, *K, *V, *Vt, *P;
    cudaGetSymbolAddress((void**)&xr, g_xr);
    cudaGetSymbolAddress((void**)&Wr, g_Wr);
    cudaGetSymbolAddress((void**)&Q, g_Q);
    cudaGetSymbolAddress((void**)&K, g_K);
    cudaGetSymbolAddress((void**)&V, g_V);
    cudaGetSymbolAddress((void**)&Vt, g_Vt);
    cudaGetSymbolAddress((void**)&P, g_P);

    const int smemBytes = STAGES * STAGE_BYTES;   // 96KB
    cudaFuncSetAttribute(mma_gemm<true, true>,
                         cudaFuncAttributeMaxDynamicSharedMemorySize, smemBytes);
    cudaFuncSetAttribute(mma_gemm<false, false>,
                         cudaFuncAttributeMaxDynamicSharedMemorySize, smemBytes);

    // 0) round inputs to tf32 (RNA) so HW mantissa truncation is exact/unbiased
    rna_kernel<<<(Bb * Ss * Dd / 4 + 255) / 256, 256>>>(x, xr, Bb * Ss * Dd / 4);
    rna_kernel<<<(Dd * Dd / 4 + 255) / 256, 256>>>(Wq, Wr + 0 * Dd * Dd, Dd * Dd / 4);
    rna_kernel<<<(Dd * Dd / 4 + 255) / 256, 256>>>(Wk, Wr + 1 * Dd * Dd, Dd * Dd / 4);
    rna_kernel<<<(Dd * Dd / 4 + 255) / 256, 256>>>(Wv, Wr + 2 * Dd * Dd, Dd * Dd / 4);

    const long long SD = (long long)Ss * Dd;
    const long long SS2 = (long long)Ss * Ss;

    // 1) projections: [8192,1024] = xr @ W^T + b (tf32-rounded outputs)
    const dim3 g1(Dd / BN, (Bb * Ss) / BM, 1);
    mma_gemm<true, true><<<g1, 256, smemBytes>>>(xr, Wr + 0 * Dd * Dd, bq, Q, Dd, Dd, 1.0f, 0, 0, 0);
    mma_gemm<true, true><<<g1, 256, smemBytes>>>(xr, Wr + 1 * Dd * Dd, bk, K, Dd, Dd, 1.0f, 0, 0, 0);
    mma_gemm<true, true><<<g1, 256, smemBytes>>>(xr, Wr + 2 * Dd * Dd, bv, V, Dd, Dd, 1.0f, 0, 0, 0);

    // 2) V transpose -> Vt [B, D, S] (K-major B for the PV GEMM)
    transpose_kernel<<<dim3(Ss / 32, Dd / 32, Bb), dim3(32, 8)>>>(V, Vt);

    // 3) scores = Q @ K^T / 32
    const dim3 g2(Ss / BN, Ss / BM, Bb);
    mma_gemm<false, false><<<g2, 256, smemBytes>>>(Q, K, nullptr, P, Ss, Dd, 0.03125f, SD, SD, SS2);

    // 4) softmax (tf32-rounded output)
    softmax_kernel<<<Bb * Ss, 256>>>(P);

    // 5) out = P @ Vt^T
    const dim3 g3(Dd / BN, Ss / BM, Bb);
    mma_gemm<false, false><<<g3, 256, smemBytes>>>(P, Vt, nullptr, out, Dd, Ss, 1.0f, SS2, SD, SD);
}

// round 4
// speedup vs baseline: 6.5661x; 1.7941x over previous
#include <cuda_runtime.h>
#include <cuda_fp16.h>
#include <cstdint>

#define Bb 4
#define Ss 2048
#define Dd 1024

#define BM 128
#define BN 128
#define BK 64                                  // fp16: 64 * 2B = 128B per row
#define STAGES 3
#define A_BYTES (BM * 128)                     // 16KB
#define STAGE_BYTES (2 * A_BYTES)              // 32KB

// ---------------- device scratch (allocation-free rule) ----------------
__device__ __align__(1024) __half g_x16[Bb * Ss * Dd];
__device__ __align__(1024) __half g_W16[3 * Dd * Dd];
__device__ __align__(1024) __half g_Q16[Bb * Ss * Dd];
__device__ __align__(1024) __half g_K16[Bb * Ss * Dd];
__device__ __align__(1024) __half g_V16[Bb * Ss * Dd];
__device__ __align__(1024) __half g_Vt16[Bb * Ss * Dd];
__device__ __align__(1024) float  g_P32[Bb * Ss * Ss];
__device__ __align__(1024) __half g_P16[Bb * Ss * Ss];

// ---------------- helpers ----------------
__device__ __forceinline__ uint32_t smem_u32(const void* p) {
    uint32_t a;
    asm("{ .reg .u64 t; cvta.to.shared.u64 t, %1; cvt.u32.u64 %0, t; }" : "=r"(a) : "l"(p));
    return a;
}
__device__ __forceinline__ void cp16(uint32_t dst, const void* src) {
    asm volatile("cp.async.cg.shared.global [%0], [%1], 16;" :: "r"(dst), "l"(src));
}
__device__ __forceinline__ void cp_commit() {
    asm volatile("cp.async.commit_group;" ::: "memory");
}
__device__ __forceinline__ void cp_wait1() {
    asm volatile("cp.async.wait_group 1;" ::: "memory");
}
__device__ __forceinline__ void ldsm4(uint32_t& r0, uint32_t& r1, uint32_t& r2, uint32_t& r3,
                                      uint32_t addr) {
    asm volatile("ldmatrix.sync.aligned.m8n8.x4.shared.b16 {%0,%1,%2,%3}, [%4];"
                 : "=r"(r0), "=r"(r1), "=r"(r2), "=r"(r3) : "r"(addr));
}
__device__ __forceinline__ void mma_f16(float* c, const uint32_t* a, uint32_t b0, uint32_t b1) {
    asm volatile(
        "mma.sync.aligned.m16n8k16.row.col.f32.f16.f16.f32 "
        "{%0,%1,%2,%3}, {%4,%5,%6,%7}, {%8,%9}, {%0,%1,%2,%3};"
        : "+f"(c[0]), "+f"(c[1]), "+f"(c[2]), "+f"(c[3])
        : "r"(a[0]), "r"(a[1]), "r"(a[2]), "r"(a[3]), "r"(b0), "r"(b1));
}

// ------- fp16 mma.sync GEMM:  C[M,N] = A[M,K] @ B[N,K]^T * alpha (+bias) -------
// A, B fp16 K-major. C either fp16 (HALF_OUT) or fp32.
template <bool BIAS, bool HALF_OUT>
__global__ void __launch_bounds__(256, 2) hgemm(
    const __half* __restrict__ A, const __half* __restrict__ Bm,
    const float* __restrict__ bias, void* __restrict__ Cv,
    int Ntot, int Ktot, float alpha,
    long long sA, long long sB, long long sC)
{
    extern __shared__ __align__(1024) char smem[];
    const uint32_t sb = smem_u32(smem);

    const int tid = threadIdx.x;
    const int lane = tid & 31;
    const int wid = tid >> 5;
    const int wm = wid & 1;        // 2 warps in M
    const int wn = wid >> 1;       // 4 warps in N

    const int rowBase = blockIdx.y * BM;
    const int colBase = blockIdx.x * BN;
    const __half* Ab = A + blockIdx.z * sA + (long long)rowBase * Ktot;
    const __half* Bg0 = Bm + blockIdx.z * sB + (long long)colBase * Ktot;

    // loader: 128 rows x 8 chunks(16B = 8 halves), 4 passes of 32 rows
    const int lr = tid >> 3;       // 0..31
    const int lc = tid & 7;        // 0..7

    const int frow = lane & 15;
    const int fkc = lane >> 4;     // k-half chunk select within a 32B (k16) step

    float acc[4][4][4];
#pragma unroll
    for (int i = 0; i < 4; i++)
#pragma unroll
        for (int j = 0; j < 4; j++)
#pragma unroll
            for (int q = 0; q < 4; q++) acc[i][j][q] = 0.0f;

    const int kIters = Ktot / BK;

    auto load_stage = [&](int buf, int kt) {
        const uint32_t sbase = sb + buf * STAGE_BYTES;
        const __half* Ag = Ab + kt * BK;
        const __half* Bg = Bg0 + kt * BK;
#pragma unroll
        for (int p = 0; p < 4; p++) {
            const int row = lr + 32 * p;
            const uint32_t off = row * 128 + ((uint32_t)(lc ^ (row & 7)) << 4);
            cp16(sbase + off, Ag + (long long)row * Ktot + lc * 8);
            cp16(sbase + A_BYTES + off, Bg + (long long)row * Ktot + lc * 8);
        }
    };

#pragma unroll
    for (int s = 0; s < STAGES - 1; s++) {
        if (s < kIters) load_stage(s, s);
        cp_commit();
    }

    int arow[4], brow[2];
#pragma unroll
    for (int mt = 0; mt < 4; mt++) arow[mt] = wm * 64 + mt * 16 + frow;
#pragma unroll
    for (int p = 0; p < 2; p++) brow[p] = wn * 32 + p * 16 + frow;

    for (int it = 0; it < kIters; it++) {
        cp_wait1();
        __syncthreads();

        const int nx = it + STAGES - 1;
        if (nx < kIters) load_stage(nx % STAGES, nx);
        cp_commit();

        const uint32_t As = sb + (it % STAGES) * STAGE_BYTES;
        const uint32_t Bs = As + A_BYTES;

#pragma unroll
        for (int ks = 0; ks < 4; ks++) {            // 4 x k16 steps = K64
            const int chunk = 2 * ks + fkc;
            uint32_t a[4][4];
#pragma unroll
            for (int mt = 0; mt < 4; mt++) {
                const uint32_t ad = As + arow[mt] * 128 +
                                    ((uint32_t)(chunk ^ (arow[mt] & 7)) << 4);
                ldsm4(a[mt][0], a[mt][1], a[mt][2], a[mt][3], ad);
            }
            uint32_t b[2][4];
#pragma unroll
            for (int p = 0; p < 2; p++) {
                const uint32_t bd = Bs + brow[p] * 128 +
                                    ((uint32_t)(chunk ^ (brow[p] & 7)) << 4);
                ldsm4(b[p][0], b[p][1], b[p][2], b[p][3], bd);
            }
#pragma unroll
            for (int mt = 0; mt < 4; mt++)
#pragma unroll
                for (int nt = 0; nt < 4; nt++) {
                    const int p = nt >> 1, o = nt & 1;
                    mma_f16(acc[mt][nt], a[mt], b[p][o], b[p][2 + o]);
                }
        }
        __syncthreads();
    }

    // ---- epilogue ----
    const int g = lane >> 2;
    const int cpair = (lane & 3) * 2;
#pragma unroll
    for (int mt = 0; mt < 4; mt++) {
#pragma unroll
        for (int nt = 0; nt < 4; nt++) {
            const int col = colBase + wn * 32 + nt * 8 + cpair;
            float bx = 0.f, by = 0.f;
            if (BIAS) { bx = bias[col]; by = bias[col + 1]; }
            const long long r0 = rowBase + wm * 64 + mt * 16 + g;
            const long long r1 = r0 + 8;
            float2 v0, v1;
            v0.x = acc[mt][nt][0] * alpha + bx;
            v0.y = acc[mt][nt][1] * alpha + by;
            v1.x = acc[mt][nt][2] * alpha + bx;
            v1.y = acc[mt][nt][3] * alpha + by;
            if (HALF_OUT) {
                __half* Cb = (__half*)Cv + blockIdx.z * sC;
                *reinterpret_cast<__half2*>(Cb + r0 * Ntot + col) = __floats2half2_rn(v0.x, v0.y);
                *reinterpret_cast<__half2*>(Cb + r1 * Ntot + col) = __floats2half2_rn(v1.x, v1.y);
            } else {
                float* Cb = (float*)Cv + blockIdx.z * sC;
                *reinterpret_cast<float2*>(Cb + r0 * Ntot + col) = v0;
                *reinterpret_cast<float2*>(Cb + r1 * Ntot + col) = v1;
            }
        }
    }
}

// ---------------- fp32 -> fp16 convert ----------------
__global__ void cvt_half_kernel(const float* __restrict__ in, __half* __restrict__ out, int n4)
{
    int i = blockIdx.x * blockDim.x + threadIdx.x;
    if (i >= n4) return;
    const float4 v = reinterpret_cast<const float4*>(in)[i];
    __half2* o = reinterpret_cast<__half2*>(out);
    o[2 * i]     = __floats2half2_rn(v.x, v.y);
    o[2 * i + 1] = __floats2half2_rn(v.z, v.w);
}

// ---------------- V transpose (fp16): Vt[b][e][s] = V[b][s][e] ----------------
__global__ void transpose_kernel(const __half* __restrict__ V, __half* __restrict__ Vt)
{
    __shared__ __half t[32][33];
    const int b = blockIdx.z;
    const int s0 = blockIdx.x * 32, e0 = blockIdx.y * 32;
    const __half* Vb = V + (long long)b * Ss * Dd;
    __half* Vtb = Vt + (long long)b * Ss * Dd;
    const int x = threadIdx.x, y = threadIdx.y;
#pragma unroll
    for (int i = 0; i < 4; i++)
        t[y + 8 * i][x] = Vb[(long long)(s0 + y + 8 * i) * Dd + e0 + x];
    __syncthreads();
#pragma unroll
    for (int i = 0; i < 4; i++)
        Vtb[(long long)(e0 + y + 8 * i) * Ss + s0 + x] = t[x][y + 8 * i];
}

// ------- row softmax over S=2048: reads fp32 scores, writes fp16 P -------
__global__ void __launch_bounds__(256) softmax_kernel(const float* __restrict__ S32,
                                                      __half* __restrict__ P16)
{
    const float* row = S32 + (long long)blockIdx.x * Ss;
    __half* orow = P16 + (long long)blockIdx.x * Ss;
    const int tid = threadIdx.x;
    const int w = tid >> 5, l = tid & 31;

    float v[8];
    float m = -1e30f;
#pragma unroll
    for (int i = 0; i < 8; i++) { v[i] = row[tid + i * 256]; m = fmaxf(m, v[i]); }
#pragma unroll
    for (int o = 16; o > 0; o >>= 1) m = fmaxf(m, __shfl_xor_sync(0xFFFFFFFFu, m, o));

    __shared__ float smax[8], ssum[8];
    if (l == 0) smax[w] = m;
    __syncthreads();
    m = smax[0];
#pragma unroll
    for (int i = 1; i < 8; i++) m = fmaxf(m, smax[i]);

    float s = 0.0f;
#pragma unroll
    for (int i = 0; i < 8; i++) { v[i] = __expf(v[i] - m); s += v[i]; }
#pragma unroll
    for (int o = 16; o > 0; o >>= 1) s += __shfl_xor_sync(0xFFFFFFFFu, s, o);
    if (l == 0) ssum[w] = s;
    __syncthreads();
    float tot = 0.0f;
#pragma unroll
    for (int i = 0; i < 8; i++) tot += ssum[i];
    const float inv = 1.0f / tot;
#pragma unroll
    for (int i = 0; i < 8; i++) orow[tid + i * 256] = __float2half_rn(v[i] * inv);
}

// ---------------- host ----------------
extern "C" void kernel_launch(void* const* d_in, const int* in_sizes, int n_in,
                              void* d_out, int out_size)
{
    const float* x  = (const float*)d_in[0];
    const float* Wq = (const float*)d_in[1];
    const float* bq = (const float*)d_in[2];
    const float* Wk = (const float*)d_in[3];
    const float* bk = (const float*)d_in[4];
    const float* Wv = (const float*)d_in[5];
    const float* bv = (const float*)d_in[6];
    float* out = (float*)d_out;

    __half *x16, *W16, *Q16, *K16, *V16, *Vt16, *P16;
    float* P32;
    cudaGetSymbolAddress((void**)&x16, g_x16);
    cudaGetSymbolAddress((void**)&W16, g_W16);
    cudaGetSymbolAddress((void**)&Q16, g_Q16);
    cudaGetSymbolAddress((void**)&K16, g_K16);
    cudaGetSymbolAddress((void**)&V16, g_V16);
    cudaGetSymbolAddress((void**)&Vt16, g_Vt16);
    cudaGetSymbolAddress((void**)&P32, g_P32);
    cudaGetSymbolAddress((void**)&P16, g_P16);

    const int smemBytes = STAGES * STAGE_BYTES;   // 96KB
    cudaFuncSetAttribute(hgemm<true, true>,
                         cudaFuncAttributeMaxDynamicSharedMemorySize, smemBytes);
    cudaFuncSetAttribute(hgemm<false, false>,
                         cudaFuncAttributeMaxDynamicSharedMemorySize, smemBytes);

    // 0) convert inputs to fp16 (RN)
    cvt_half_kernel<<<(Bb * Ss * Dd / 4 + 255) / 256, 256>>>(x, x16, Bb * Ss * Dd / 4);
    cvt_half_kernel<<<(Dd * Dd / 4 + 255) / 256, 256>>>(Wq, W16 + 0 * Dd * Dd, Dd * Dd / 4);
    cvt_half_kernel<<<(Dd * Dd / 4 + 255) / 256, 256>>>(Wk, W16 + 1 * Dd * Dd, Dd * Dd / 4);
    cvt_half_kernel<<<(Dd * Dd / 4 + 255) / 256, 256>>>(Wv, W16 + 2 * Dd * Dd, Dd * Dd / 4);

    const long long SD = (long long)Ss * Dd;
    const long long SS2 = (long long)Ss * Ss;

    // 1) projections: [8192,1024] = x16 @ W^T + b -> fp16 Q/K/V
    const dim3 g1(Dd / BN, (Bb * Ss) / BM, 1);
    hgemm<true, true><<<g1, 256, smemBytes>>>(x16, W16 + 0 * Dd * Dd, bq, Q16, Dd, Dd, 1.0f, 0, 0, 0);
    hgemm<true, true><<<g1, 256, smemBytes>>>(x16, W16 + 1 * Dd * Dd, bk, K16, Dd, Dd, 1.0f, 0, 0, 0);
    hgemm<true, true><<<g1, 256, smemBytes>>>(x16, W16 + 2 * Dd * Dd, bv, V16, Dd, Dd, 1.0f, 0, 0, 0);

    // 2) V transpose -> Vt [B, D, S] (K-major B for PV)
    transpose_kernel<<<dim3(Ss / 32, Dd / 32, Bb), dim3(32, 8)>>>(V16, Vt16);

    // 3) scores = Q @ K^T / 32  -> fp32 (protect softmax numerics)
    const dim3 g2(Ss / BN, Ss / BM, Bb);
    hgemm<false, false><<<g2, 256, smemBytes>>>(Q16, K16, nullptr, P32, Ss, Dd, 0.03125f, SD, SD, SS2);

    // 4) softmax fp32 -> fp16 P
    softmax_kernel<<<Bb * Ss, 256>>>(P32, P16);

    // 5) out = P16 @ Vt16^T -> fp32
    const dim3 g3(Dd / BN, Ss / BM, Bb);
    hgemm<false, false><<<g3, 256, smemBytes>>>(P16, Vt16, nullptr, out, Dd, Ss, 1.0f, SS2, SD, SD);
}